// round 4
// baseline (speedup 1.0000x reference)
#include <cuda_runtime.h>
#include <math_constants.h>

#define EMBED    512
#define MAXLEN   2048
#define B2       256
#define TILE     128               // tokens per energy CTA
#define NTILES   (MAXLEN / TILE)   // 16
#define ETHREADS 512
#define EWARPS   (ETHREADS / 32)   // 16
#define PBLK     64                // CTAs for prep
#define PROWS    (EMBED / PBLK)    // 8 W-rows per prep CTA

// Folded linear: v = W^T * weight_vec, c = bias . weight_vec
__device__ float g_v[EMBED];
__device__ float g_c;
__device__ float g_partial[PBLK][EMBED];
__device__ unsigned int g_cnt;                 // zero-init, self-resetting
__device__ unsigned int g_row_cnt[B2];         // per-row tile completion
__device__ float g_energy[B2 * MAXLEN];        // 2 MB static scratch

// ---------------------------------------------------------------------------
// Prep (single launch): 64 CTAs x 512 threads; each CTA folds 8 rows of W.
// Last CTA combines the 64 partials (L2-resident) and the bias dot.
// ---------------------------------------------------------------------------
__global__ __launch_bounds__(EMBED)
void prep_kernel(const float* __restrict__ W,
                 const float* __restrict__ bias,
                 const float* __restrict__ wv) {
    __shared__ float swv[PROWS];
    __shared__ bool  s_last;
    const int d   = threadIdx.x;          // 0..511
    const int blk = blockIdx.x;
    const int e0  = blk * PROWS;
    if (d < PROWS) swv[d] = wv[e0 + d];
    __syncthreads();

    float s = 0.0f;
    #pragma unroll
    for (int e = 0; e < PROWS; ++e)
        s += W[(size_t)(e0 + e) * EMBED + d] * swv[e];   // 128B coalesced
    g_partial[blk][d] = s;

    __threadfence();
    if (d == 0) {
        unsigned int prev = atomicAdd(&g_cnt, 1u);
        s_last = (prev == PBLK - 1);
    }
    __syncthreads();
    if (!s_last) return;
    __threadfence();

    float acc = 0.0f;
    #pragma unroll
    for (int p = 0; p < PBLK; ++p) acc += g_partial[p][d];
    g_v[d] = acc;

    __shared__ float sred[EMBED];
    sred[d] = bias[d] * wv[d];
    __syncthreads();
    for (int stride = EMBED / 2; stride > 0; stride >>= 1) {
        if (d < stride) sred[d] += sred[d + stride];
        __syncthreads();
    }
    if (d == 0) { g_c = sred[0]; g_cnt = 0u; }   // reset for graph replay
}

// ---------------------------------------------------------------------------
// Energies + fused per-row softmax.
// grid (NTILES, B2): each CTA does 128 tokens of one row (skipping past the
// ragged length). The LAST finishing tile-CTA of each row performs that
// row's masked softmax from the L2-hot energies and writes the output.
// ---------------------------------------------------------------------------
__global__ __launch_bounds__(ETHREADS)
void energy_softmax_kernel(const float* __restrict__ q,
                           const int*   __restrict__ lens,
                           float*       __restrict__ out) {
    const int b   = blockIdx.y;
    const int len = __ldg(lens + b);
    const int l0  = blockIdx.x * TILE;
    if (l0 >= len) return;                // empty tile: zero DRAM traffic

    __shared__ float sv[EMBED];
    __shared__ float se[MAXLEN];
    __shared__ float sred[EWARPS];
    __shared__ bool  s_do_softmax;

    const int tid  = threadIdx.x;
    const int warp = tid >> 5;
    const int lane = tid & 31;

    for (int i = tid; i < EMBED; i += ETHREADS) sv[i] = g_v[i];
    __syncthreads();

    const float  c    = g_c;
    const float4* __restrict__ sv4  = (const float4*)sv;
    const float4* __restrict__ qrow =
        (const float4*)(q + (size_t)b * MAXLEN * EMBED);
    const int end = min(l0 + TILE, len);

    float4 vv[4];
    #pragma unroll
    for (int k = 0; k < 4; ++k) vv[k] = sv4[lane + 32 * k];

    float* __restrict__ erow = g_energy + (size_t)b * MAXLEN;

    for (int l = l0 + warp; l < end; l += 2 * EWARPS) {
        const int  l2   = l + EWARPS;
        const bool has2 = (l2 < end);
        const float4* __restrict__ qp0 = qrow + (size_t)l  * (EMBED / 4);
        const float4* __restrict__ qp1 = qrow + (size_t)l2 * (EMBED / 4);

        float4 a0[4], a1[4];
        #pragma unroll
        for (int k = 0; k < 4; ++k) a0[k] = __ldcs(qp0 + lane + 32 * k);
        if (has2) {
            #pragma unroll
            for (int k = 0; k < 4; ++k) a1[k] = __ldcs(qp1 + lane + 32 * k);
        }

        float s0 = 0.0f, s1 = 0.0f;
        #pragma unroll
        for (int k = 0; k < 4; ++k)
            s0 += a0[k].x * vv[k].x + a0[k].y * vv[k].y
                + a0[k].z * vv[k].z + a0[k].w * vv[k].w;
        if (has2) {
            #pragma unroll
            for (int k = 0; k < 4; ++k)
                s1 += a1[k].x * vv[k].x + a1[k].y * vv[k].y
                    + a1[k].z * vv[k].z + a1[k].w * vv[k].w;
        }

        #pragma unroll
        for (int off = 16; off > 0; off >>= 1) {
            s0 += __shfl_xor_sync(0xffffffffu, s0, off);
            s1 += __shfl_xor_sync(0xffffffffu, s1, off);
        }
        if (lane == 0) {
            erow[l] = s0 + c;
            if (has2) erow[l2] = s1 + c;
        }
    }

    // ---- row completion: last valid tile-CTA runs the softmax ----
    __threadfence();          // publish energy writes
    __syncthreads();
    const int ntiles_valid = (len + TILE - 1) / TILE;
    if (tid == 0) {
        unsigned int prev = atomicAdd(&g_row_cnt[b], 1u);
        s_do_softmax = (prev == (unsigned)(ntiles_valid - 1));
    }
    __syncthreads();
    if (!s_do_softmax) return;
    __threadfence();          // acquire other CTAs' energy writes

    // ---- masked softmax for row b (energies are L2-hot) ----
    float m = -CUDART_INF_F;
    for (int l = tid; l < len; l += ETHREADS) {
        float e = erow[l];
        se[l] = e;
        m = fmaxf(m, e);
    }
    #pragma unroll
    for (int off = 16; off > 0; off >>= 1)
        m = fmaxf(m, __shfl_xor_sync(0xffffffffu, m, off));
    if (lane == 0) sred[warp] = m;
    __syncthreads();
    if (warp == 0) {
        float mm = (lane < EWARPS) ? sred[lane] : -CUDART_INF_F;
        #pragma unroll
        for (int off = 16; off > 0; off >>= 1)
            mm = fmaxf(mm, __shfl_xor_sync(0xffffffffu, mm, off));
        if (lane == 0) sred[0] = mm;
    }
    __syncthreads();
    m = sred[0];
    __syncthreads();

    float ssum = 0.0f;
    for (int l = tid; l < len; l += ETHREADS) {
        float e = __expf(se[l] - m);
        se[l] = e;
        ssum += e;
    }
    #pragma unroll
    for (int off = 16; off > 0; off >>= 1)
        ssum += __shfl_xor_sync(0xffffffffu, ssum, off);
    if (lane == 0) sred[warp] = ssum;
    __syncthreads();
    if (warp == 0) {
        float t = (lane < EWARPS) ? sred[lane] : 0.0f;
        #pragma unroll
        for (int off = 16; off > 0; off >>= 1)
            t += __shfl_xor_sync(0xffffffffu, t, off);
        if (lane == 0) sred[0] = t;
    }
    __syncthreads();
    const float inv = 1.0f / sred[0];

    // vectorized masked write: each thread owns one float4
    float4* __restrict__ orow4 = (float4*)(out + (size_t)b * MAXLEN);
    const int base = tid * 4;    // 512 * 4 = 2048
    float4 o;
    o.x = (base + 0 < len) ? se[base + 0] * inv : 0.0f;
    o.y = (base + 1 < len) ? se[base + 1] * inv : 0.0f;
    o.z = (base + 2 < len) ? se[base + 2] * inv : 0.0f;
    o.w = (base + 3 < len) ? se[base + 3] * inv : 0.0f;
    orow4[tid] = o;

    if (tid == 0) g_row_cnt[b] = 0u;     // reset for graph replay
}

// ---------------------------------------------------------------------------
// Launch. inputs: questions, questions_lens, lin_w, lin_b, weight_vec
// ---------------------------------------------------------------------------
extern "C" void kernel_launch(void* const* d_in, const int* in_sizes, int n_in,
                              void* d_out, int out_size) {
    const float* questions = (const float*)d_in[0];
    const int*   lens      = (const int*)  d_in[1];
    const float* lin_w     = (const float*)d_in[2];
    const float* lin_b     = (const float*)d_in[3];
    const float* wv        = (const float*)d_in[4];
    float* out = (float*)d_out;

    prep_kernel<<<PBLK, EMBED>>>(lin_w, lin_b, wv);

    dim3 egrid(NTILES, B2);
    energy_softmax_kernel<<<egrid, ETHREADS>>>(questions, lens, out);
}

// round 5
// speedup vs baseline: 1.0622x; 1.0622x over previous
#include <cuda_runtime.h>
#include <math_constants.h>

#define EMBED    512
#define MAXLEN   2048
#define B2       256
#define TILE     128               // tokens per energy CTA
#define NTILES   (MAXLEN / TILE)   // 16
#define ETHREADS 512
#define EWARPS   (ETHREADS / 32)   // 16
#define PBLK     64                // CTAs for prep
#define PROWS    (EMBED / PBLK)    // 8 W-rows per prep CTA

// Folded linear: v = W^T * weight_vec, c = bias . weight_vec
__device__ float g_v[EMBED];
__device__ float g_c;
__device__ float g_partial[PBLK][EMBED];
__device__ unsigned int g_cnt;            // zero-init, self-resetting
__device__ float g_energy[B2 * MAXLEN];   // 2 MB static scratch (L2-resident)

// ---------------------------------------------------------------------------
// Prep (single launch): 64 CTAs x 512 threads; each CTA folds 8 rows of W.
// Last CTA combines the 64 partials (L2-resident) and the bias dot.
// ---------------------------------------------------------------------------
__global__ __launch_bounds__(EMBED)
void prep_kernel(const float* __restrict__ W,
                 const float* __restrict__ bias,
                 const float* __restrict__ wv) {
    __shared__ float swv[PROWS];
    __shared__ bool  s_last;
    const int d   = threadIdx.x;          // 0..511
    const int blk = blockIdx.x;
    const int e0  = blk * PROWS;
    if (d < PROWS) swv[d] = wv[e0 + d];
    __syncthreads();

    float s = 0.0f;
    #pragma unroll
    for (int e = 0; e < PROWS; ++e)
        s += W[(size_t)(e0 + e) * EMBED + d] * swv[e];   // 128B coalesced
    g_partial[blk][d] = s;

    __threadfence();
    if (d == 0) {
        unsigned int prev = atomicAdd(&g_cnt, 1u);
        s_last = (prev == PBLK - 1);
    }
    __syncthreads();
    if (!s_last) return;
    __threadfence();

    float acc = 0.0f;
    #pragma unroll
    for (int p = 0; p < PBLK; ++p) acc += g_partial[p][d];
    g_v[d] = acc;

    __shared__ float sred[EMBED];
    sred[d] = bias[d] * wv[d];
    __syncthreads();
    for (int stride = EMBED / 2; stride > 0; stride >>= 1) {
        if (d < stride) sred[d] += sred[d + stride];
        __syncthreads();
    }
    if (d == 0) { g_c = sred[0]; g_cnt = 0u; }   // reset for graph replay
}

// ---------------------------------------------------------------------------
// Energies: grid (NTILES, B2). Lean streaming kernel — 2 KB smem, minimal
// registers, warp-per-token with 2 tokens in flight (8 LDG.128/lane),
// streaming loads, skipping tiles past the ragged length.
// ---------------------------------------------------------------------------
__global__ __launch_bounds__(ETHREADS)
void energy_kernel(const float* __restrict__ q,
                   const int*   __restrict__ lens) {
    const int b   = blockIdx.y;
    const int len = __ldg(lens + b);
    const int l0  = blockIdx.x * TILE;
    if (l0 >= len) return;                // empty tile: zero DRAM traffic

    __shared__ float sv[EMBED];
    const int tid  = threadIdx.x;
    const int warp = tid >> 5;
    const int lane = tid & 31;

    for (int i = tid; i < EMBED; i += ETHREADS) sv[i] = g_v[i];
    __syncthreads();

    const float  c    = g_c;
    const float4* __restrict__ sv4  = (const float4*)sv;
    const float4* __restrict__ qrow =
        (const float4*)(q + (size_t)b * MAXLEN * EMBED);
    const int end = min(l0 + TILE, len);

    float4 vv[4];
    #pragma unroll
    for (int k = 0; k < 4; ++k) vv[k] = sv4[lane + 32 * k];

    float* __restrict__ erow = g_energy + (size_t)b * MAXLEN;

    for (int l = l0 + warp; l < end; l += 2 * EWARPS) {
        const int  l2   = l + EWARPS;
        const bool has2 = (l2 < end);
        const float4* __restrict__ qp0 = qrow + (size_t)l  * (EMBED / 4);
        const float4* __restrict__ qp1 = qrow + (size_t)l2 * (EMBED / 4);

        float4 a0[4], a1[4];
        #pragma unroll
        for (int k = 0; k < 4; ++k) a0[k] = __ldcs(qp0 + lane + 32 * k);
        if (has2) {
            #pragma unroll
            for (int k = 0; k < 4; ++k) a1[k] = __ldcs(qp1 + lane + 32 * k);
        }

        float s0 = 0.0f, s1 = 0.0f;
        #pragma unroll
        for (int k = 0; k < 4; ++k)
            s0 += a0[k].x * vv[k].x + a0[k].y * vv[k].y
                + a0[k].z * vv[k].z + a0[k].w * vv[k].w;
        if (has2) {
            #pragma unroll
            for (int k = 0; k < 4; ++k)
                s1 += a1[k].x * vv[k].x + a1[k].y * vv[k].y
                    + a1[k].z * vv[k].z + a1[k].w * vv[k].w;
        }

        #pragma unroll
        for (int off = 16; off > 0; off >>= 1) {
            s0 += __shfl_xor_sync(0xffffffffu, s0, off);
            s1 += __shfl_xor_sync(0xffffffffu, s1, off);
        }
        if (lane == 0) {
            erow[l] = s0 + c;
            if (has2) erow[l2] = s1 + c;
        }
    }
}

// ---------------------------------------------------------------------------
// Softmax: one CTA (512 threads) per row. Energies are L2-hot. float4 stores.
// ---------------------------------------------------------------------------
#define STHREADS 512
#define SWARPS   (STHREADS / 32)   // 16
__global__ __launch_bounds__(STHREADS)
void softmax_kernel(const int* __restrict__ lens,
                    float*     __restrict__ out) {
    __shared__ float se[MAXLEN];
    __shared__ float sred[SWARPS];

    const int b    = blockIdx.x;
    const int len  = __ldg(lens + b);
    const int tid  = threadIdx.x;
    const int warp = tid >> 5;
    const int lane = tid & 31;
    const float* __restrict__ erow = g_energy + (size_t)b * MAXLEN;

    // load valid energies + max
    float m = -CUDART_INF_F;
    for (int l = tid; l < len; l += STHREADS) {
        float e = erow[l];
        se[l] = e;
        m = fmaxf(m, e);
    }
    #pragma unroll
    for (int off = 16; off > 0; off >>= 1)
        m = fmaxf(m, __shfl_xor_sync(0xffffffffu, m, off));
    if (lane == 0) sred[warp] = m;
    __syncthreads();
    if (warp == 0) {
        float mm = (lane < SWARPS) ? sred[lane] : -CUDART_INF_F;
        #pragma unroll
        for (int off = 16; off > 0; off >>= 1)
            mm = fmaxf(mm, __shfl_xor_sync(0xffffffffu, mm, off));
        if (lane == 0) sred[0] = mm;
    }
    __syncthreads();
    m = sred[0];
    __syncthreads();

    // exp + sum
    float ssum = 0.0f;
    for (int l = tid; l < len; l += STHREADS) {
        float e = __expf(se[l] - m);
        se[l] = e;
        ssum += e;
    }
    #pragma unroll
    for (int off = 16; off > 0; off >>= 1)
        ssum += __shfl_xor_sync(0xffffffffu, ssum, off);
    if (lane == 0) sred[warp] = ssum;
    __syncthreads();
    if (warp == 0) {
        float t = (lane < SWARPS) ? sred[lane] : 0.0f;
        #pragma unroll
        for (int off = 16; off > 0; off >>= 1)
            t += __shfl_xor_sync(0xffffffffu, t, off);
        if (lane == 0) sred[0] = t;
    }
    __syncthreads();
    const float inv = 1.0f / sred[0];

    // vectorized masked write: each thread owns one float4
    float4* __restrict__ orow4 = (float4*)(out + (size_t)b * MAXLEN);
    const int base = tid * 4;    // 512 * 4 = 2048
    float4 o;
    o.x = (base + 0 < len) ? se[base + 0] * inv : 0.0f;
    o.y = (base + 1 < len) ? se[base + 1] * inv : 0.0f;
    o.z = (base + 2 < len) ? se[base + 2] * inv : 0.0f;
    o.w = (base + 3 < len) ? se[base + 3] * inv : 0.0f;
    orow4[tid] = o;
}

// ---------------------------------------------------------------------------
// Launch. inputs: questions, questions_lens, lin_w, lin_b, weight_vec
// ---------------------------------------------------------------------------
extern "C" void kernel_launch(void* const* d_in, const int* in_sizes, int n_in,
                              void* d_out, int out_size) {
    const float* questions = (const float*)d_in[0];
    const int*   lens      = (const int*)  d_in[1];
    const float* lin_w     = (const float*)d_in[2];
    const float* lin_b     = (const float*)d_in[3];
    const float* wv        = (const float*)d_in[4];
    float* out = (float*)d_out;

    prep_kernel<<<PBLK, EMBED>>>(lin_w, lin_b, wv);

    dim3 egrid(NTILES, B2);
    energy_kernel<<<egrid, ETHREADS>>>(questions, lens);
    softmax_kernel<<<B2, STHREADS>>>(lens, out);
}

// round 6
// speedup vs baseline: 1.1099x; 1.0449x over previous
#include <cuda_runtime.h>
#include <math_constants.h>

#define EMBED    512
#define MAXLEN   2048
#define B2       256
#define TILE     128               // tokens per energy CTA
#define NTILES   (MAXLEN / TILE)   // 16
#define ETHREADS 512
#define EWARPS   (ETHREADS / 32)   // 16
#define PBLK     64                // prep CTAs
#define PD       (EMBED / PBLK)    // 8 output dims per prep CTA

// Folded linear: v = W^T * weight_vec, c = bias . weight_vec
__device__ float g_v[EMBED];
__device__ float g_c;
__device__ float g_energy[B2 * MAXLEN];   // 2 MB static scratch (L2-resident)

// ---------------------------------------------------------------------------
// Prep (single pass, no inter-CTA deps): 64 CTAs x 512 threads.
// CTA blk owns output dims d0..d0+7 and reduces over ALL e in-CTA:
//   thread t handles e=t: a[j] = W[t*EMBED + d0+j] * wv[t]
// then warp-shuffle + smem tree reduce the 8 components. CTA 0 also
// computes c = bias . wv (it holds every e already).
// ---------------------------------------------------------------------------
__global__ __launch_bounds__(EMBED)
void prep_kernel(const float* __restrict__ W,
                 const float* __restrict__ bias,
                 const float* __restrict__ wv) {
    __shared__ float sp[16][PD];     // per-warp partial sums (16 warps)
    __shared__ float sc[16];         // per-warp partials for c (CTA 0)

    const int t    = threadIdx.x;    // e index
    const int warp = t >> 5;
    const int lane = t & 31;
    const int d0   = blockIdx.x * PD;

    const float w = wv[t];
    const float4* __restrict__ Wp =
        (const float4*)(W + (size_t)t * EMBED + d0);
    float4 w0 = Wp[0];
    float4 w1 = Wp[1];

    float a[PD];
    a[0] = w0.x * w; a[1] = w0.y * w; a[2] = w0.z * w; a[3] = w0.w * w;
    a[4] = w1.x * w; a[5] = w1.y * w; a[6] = w1.z * w; a[7] = w1.w * w;

    #pragma unroll
    for (int off = 16; off > 0; off >>= 1) {
        #pragma unroll
        for (int j = 0; j < PD; ++j)
            a[j] += __shfl_xor_sync(0xffffffffu, a[j], off);
    }
    if (lane == 0) {
        #pragma unroll
        for (int j = 0; j < PD; ++j) sp[warp][j] = a[j];
    }

    // CTA 0: bias dot in parallel
    float cpart = 0.0f;
    if (blockIdx.x == 0) {
        cpart = bias[t] * w;
        #pragma unroll
        for (int off = 16; off > 0; off >>= 1)
            cpart += __shfl_xor_sync(0xffffffffu, cpart, off);
        if (lane == 0) sc[warp] = cpart;
    }
    __syncthreads();

    // final combine: first PD threads each own one output dim
    if (t < PD) {
        float s = 0.0f;
        #pragma unroll
        for (int wdx = 0; wdx < 16; ++wdx) s += sp[wdx][t];
        g_v[d0 + t] = s;
    }
    if (blockIdx.x == 0 && t == EMBED - 1) {
        float s = 0.0f;
        #pragma unroll
        for (int wdx = 0; wdx < 16; ++wdx) s += sc[wdx];
        g_c = s;
    }
}

// ---------------------------------------------------------------------------
// Energies: grid (NTILES, B2). Lean streaming kernel — 2 KB smem,
// warp-per-token with 2 tokens in flight (8 LDG.128/lane), streaming loads,
// skipping tiles past the ragged length.
// ---------------------------------------------------------------------------
__global__ __launch_bounds__(ETHREADS)
void energy_kernel(const float* __restrict__ q,
                   const int*   __restrict__ lens) {
    const int b   = blockIdx.y;
    const int len = __ldg(lens + b);
    const int l0  = blockIdx.x * TILE;
    if (l0 >= len) return;                // empty tile: zero DRAM traffic

    __shared__ float sv[EMBED];
    const int tid  = threadIdx.x;
    const int warp = tid >> 5;
    const int lane = tid & 31;

    for (int i = tid; i < EMBED; i += ETHREADS) sv[i] = g_v[i];
    __syncthreads();

    const float  c    = g_c;
    const float4* __restrict__ sv4  = (const float4*)sv;
    const float4* __restrict__ qrow =
        (const float4*)(q + (size_t)b * MAXLEN * EMBED);
    const int end = min(l0 + TILE, len);

    float4 vv[4];
    #pragma unroll
    for (int k = 0; k < 4; ++k) vv[k] = sv4[lane + 32 * k];

    float* __restrict__ erow = g_energy + (size_t)b * MAXLEN;

    for (int l = l0 + warp; l < end; l += 2 * EWARPS) {
        const int  l2   = l + EWARPS;
        const bool has2 = (l2 < end);
        const float4* __restrict__ qp0 = qrow + (size_t)l  * (EMBED / 4);
        const float4* __restrict__ qp1 = qrow + (size_t)l2 * (EMBED / 4);

        float4 a0[4], a1[4];
        #pragma unroll
        for (int k = 0; k < 4; ++k) a0[k] = __ldcs(qp0 + lane + 32 * k);
        if (has2) {
            #pragma unroll
            for (int k = 0; k < 4; ++k) a1[k] = __ldcs(qp1 + lane + 32 * k);
        }

        float s0 = 0.0f, s1 = 0.0f;
        #pragma unroll
        for (int k = 0; k < 4; ++k)
            s0 += a0[k].x * vv[k].x + a0[k].y * vv[k].y
                + a0[k].z * vv[k].z + a0[k].w * vv[k].w;
        if (has2) {
            #pragma unroll
            for (int k = 0; k < 4; ++k)
                s1 += a1[k].x * vv[k].x + a1[k].y * vv[k].y
                    + a1[k].z * vv[k].z + a1[k].w * vv[k].w;
        }

        #pragma unroll
        for (int off = 16; off > 0; off >>= 1) {
            s0 += __shfl_xor_sync(0xffffffffu, s0, off);
            s1 += __shfl_xor_sync(0xffffffffu, s1, off);
        }
        if (lane == 0) {
            erow[l] = s0 + c;
            if (has2) erow[l2] = s1 + c;
        }
    }
}

// ---------------------------------------------------------------------------
// Softmax: one CTA (512 threads) per row, single pass. Each thread owns one
// output float4 (512*4 = 2048), kept in registers the whole time.
// ---------------------------------------------------------------------------
#define STHREADS 512
#define SWARPS   (STHREADS / 32)   // 16
__global__ __launch_bounds__(STHREADS)
void softmax_kernel(const int* __restrict__ lens,
                    float*     __restrict__ out) {
    __shared__ float sred[SWARPS];

    const int b    = blockIdx.x;
    const int len  = __ldg(lens + b);
    const int tid  = threadIdx.x;
    const int warp = tid >> 5;
    const int lane = tid & 31;
    const int base = tid * 4;

    const float4* __restrict__ erow4 =
        (const float4*)(g_energy + (size_t)b * MAXLEN);

    // load owned energies (masked comps never used)
    float4 e = erow4[tid];
    const bool v0 = (base + 0 < len), v1 = (base + 1 < len),
               v2 = (base + 2 < len), v3 = (base + 3 < len);

    // block max
    float m = -CUDART_INF_F;
    if (v0) m = fmaxf(m, e.x);
    if (v1) m = fmaxf(m, e.y);
    if (v2) m = fmaxf(m, e.z);
    if (v3) m = fmaxf(m, e.w);
    #pragma unroll
    for (int off = 16; off > 0; off >>= 1)
        m = fmaxf(m, __shfl_xor_sync(0xffffffffu, m, off));
    if (lane == 0) sred[warp] = m;
    __syncthreads();
    {
        float mm = sred[lane & (SWARPS - 1)];   // 16 warps
        #pragma unroll
        for (int off = 8; off > 0; off >>= 1)
            mm = fmaxf(mm, __shfl_xor_sync(0xffffffffu, mm, off));
        m = mm;
    }
    __syncthreads();

    // exp in registers + block sum
    e.x = v0 ? __expf(e.x - m) : 0.0f;
    e.y = v1 ? __expf(e.y - m) : 0.0f;
    e.z = v2 ? __expf(e.z - m) : 0.0f;
    e.w = v3 ? __expf(e.w - m) : 0.0f;
    float ssum = e.x + e.y + e.z + e.w;
    #pragma unroll
    for (int off = 16; off > 0; off >>= 1)
        ssum += __shfl_xor_sync(0xffffffffu, ssum, off);
    if (lane == 0) sred[warp] = ssum;
    __syncthreads();
    {
        float t = sred[lane & (SWARPS - 1)];
        #pragma unroll
        for (int off = 8; off > 0; off >>= 1)
            t += __shfl_xor_sync(0xffffffffu, t, off);
        ssum = t;
    }
    const float inv = 1.0f / ssum;

    float4 o;
    o.x = e.x * inv; o.y = e.y * inv; o.z = e.z * inv; o.w = e.w * inv;
    ((float4*)(out + (size_t)b * MAXLEN))[tid] = o;
}

// ---------------------------------------------------------------------------
// Launch. inputs: questions, questions_lens, lin_w, lin_b, weight_vec
// ---------------------------------------------------------------------------
extern "C" void kernel_launch(void* const* d_in, const int* in_sizes, int n_in,
                              void* d_out, int out_size) {
    const float* questions = (const float*)d_in[0];
    const int*   lens      = (const int*)  d_in[1];
    const float* lin_w     = (const float*)d_in[2];
    const float* lin_b     = (const float*)d_in[3];
    const float* wv        = (const float*)d_in[4];
    float* out = (float*)d_out;

    prep_kernel<<<PBLK, EMBED>>>(lin_w, lin_b, wv);

    dim3 egrid(NTILES, B2);
    energy_kernel<<<egrid, ETHREADS>>>(questions, lens);
    softmax_kernel<<<B2, STHREADS>>>(lens, out);
}

// round 7
// speedup vs baseline: 1.1369x; 1.0244x over previous
#include <cuda_runtime.h>
#include <math_constants.h>

#define EMBED    512
#define MAXLEN   2048
#define B2       256
#define TILE     128               // tokens per energy CTA
#define NTILES   (MAXLEN / TILE)   // 16
#define ETHREADS 512
#define EWARPS   (ETHREADS / 32)   // 16
#define PBLK     64                // prep CTAs
#define PD       (EMBED / PBLK)    // 8 output dims per prep CTA

// Folded linear: v = W^T * weight_vec, c = bias . weight_vec
__device__ float g_v[EMBED];
__device__ float g_c;
__device__ float g_energy[B2 * MAXLEN];   // 2 MB static scratch (L2-resident)

// ---------------------------------------------------------------------------
// Prep (single pass): CTA blk owns output dims d0..d0+7, reduces over all e.
// Triggers programmatic launch completion for the PDL-chained energy kernel.
// ---------------------------------------------------------------------------
__global__ __launch_bounds__(EMBED)
void prep_kernel(const float* __restrict__ W,
                 const float* __restrict__ bias,
                 const float* __restrict__ wv) {
    __shared__ float sp[16][PD];     // per-warp partials (16 warps)
    __shared__ float sc[16];         // per-warp partials for c (CTA 0)

    const int t    = threadIdx.x;    // e index
    const int warp = t >> 5;
    const int lane = t & 31;
    const int d0   = blockIdx.x * PD;

    const float w = wv[t];
    const float4* __restrict__ Wp =
        (const float4*)(W + (size_t)t * EMBED + d0);
    float4 w0 = Wp[0];
    float4 w1 = Wp[1];

    float a[PD];
    a[0] = w0.x * w; a[1] = w0.y * w; a[2] = w0.z * w; a[3] = w0.w * w;
    a[4] = w1.x * w; a[5] = w1.y * w; a[6] = w1.z * w; a[7] = w1.w * w;

    #pragma unroll
    for (int off = 16; off > 0; off >>= 1) {
        #pragma unroll
        for (int j = 0; j < PD; ++j)
            a[j] += __shfl_xor_sync(0xffffffffu, a[j], off);
    }
    if (lane == 0) {
        #pragma unroll
        for (int j = 0; j < PD; ++j) sp[warp][j] = a[j];
    }

    float cpart = 0.0f;
    if (blockIdx.x == 0) {
        cpart = bias[t] * w;
        #pragma unroll
        for (int off = 16; off > 0; off >>= 1)
            cpart += __shfl_xor_sync(0xffffffffu, cpart, off);
        if (lane == 0) sc[warp] = cpart;
    }
    __syncthreads();

    if (t < PD) {
        float s = 0.0f;
        #pragma unroll
        for (int wdx = 0; wdx < 16; ++wdx) s += sp[wdx][t];
        g_v[d0 + t] = s;
    }
    if (blockIdx.x == 0 && t == EMBED - 1) {
        float s = 0.0f;
        #pragma unroll
        for (int wdx = 0; wdx < 16; ++wdx) s += sc[wdx];
        g_c = s;
    }
#if __CUDA_ARCH__ >= 900
    cudaTriggerProgrammaticLaunchCompletion();
#endif
}

// ---------------------------------------------------------------------------
// Energies: grid (NTILES, B2). PDL secondary: prologue + first-iteration
// q-loads run before cudaGridDependencySynchronize(); only the v-read waits
// on prep. No smem; v comes from L2-broadcast g_v reads.
// ---------------------------------------------------------------------------
__global__ __launch_bounds__(ETHREADS)
void energy_kernel(const float* __restrict__ q,
                   const int*   __restrict__ lens) {
    const int b   = blockIdx.y;
    const int len = __ldg(lens + b);
    const int l0  = blockIdx.x * TILE;
    if (l0 >= len) return;                // empty tile: zero DRAM traffic

    const int tid  = threadIdx.x;
    const int warp = tid >> 5;
    const int lane = tid & 31;

    const float4* __restrict__ qrow =
        (const float4*)(q + (size_t)b * MAXLEN * EMBED);
    const int end = min(l0 + TILE, len);

    // ---- prefetch first pair of tokens (independent of prep's output) ----
    const int l  = l0 + warp;
    const int lB = l + EWARPS;
    const bool hasA = (l  < end);
    const bool hasB = (lB < end);
    float4 a0[4], a1[4];
    if (hasA) {
        const float4* __restrict__ qp = qrow + (size_t)l * (EMBED / 4);
        #pragma unroll
        for (int k = 0; k < 4; ++k) a0[k] = __ldcs(qp + lane + 32 * k);
    }
    if (hasB) {
        const float4* __restrict__ qp = qrow + (size_t)lB * (EMBED / 4);
        #pragma unroll
        for (int k = 0; k < 4; ++k) a1[k] = __ldcs(qp + lane + 32 * k);
    }

#if __CUDA_ARCH__ >= 900
    cudaGridDependencySynchronize();      // wait for prep results
#endif

    float4 vv[4];
    const float4* __restrict__ gv4 = (const float4*)g_v;
    #pragma unroll
    for (int k = 0; k < 4; ++k) vv[k] = gv4[lane + 32 * k];
    const float c = g_c;

    float* __restrict__ erow = g_energy + (size_t)b * MAXLEN;

    // ---- first (prefetched) iteration ----
    {
        float s0 = 0.0f, s1 = 0.0f;
        if (hasA) {
            #pragma unroll
            for (int k = 0; k < 4; ++k)
                s0 += a0[k].x * vv[k].x + a0[k].y * vv[k].y
                    + a0[k].z * vv[k].z + a0[k].w * vv[k].w;
        }
        if (hasB) {
            #pragma unroll
            for (int k = 0; k < 4; ++k)
                s1 += a1[k].x * vv[k].x + a1[k].y * vv[k].y
                    + a1[k].z * vv[k].z + a1[k].w * vv[k].w;
        }
        #pragma unroll
        for (int off = 16; off > 0; off >>= 1) {
            s0 += __shfl_xor_sync(0xffffffffu, s0, off);
            s1 += __shfl_xor_sync(0xffffffffu, s1, off);
        }
        if (lane == 0) {
            if (hasA) erow[l]  = s0 + c;
            if (hasB) erow[lB] = s1 + c;
        }
    }

    // ---- remaining iterations ----
    for (int ll = l + 2 * EWARPS; ll < end; ll += 2 * EWARPS) {
        const int  ll2  = ll + EWARPS;
        const bool has2 = (ll2 < end);
        const float4* __restrict__ qp0 = qrow + (size_t)ll  * (EMBED / 4);
        const float4* __restrict__ qp1 = qrow + (size_t)ll2 * (EMBED / 4);

        float4 b0[4], b1[4];
        #pragma unroll
        for (int k = 0; k < 4; ++k) b0[k] = __ldcs(qp0 + lane + 32 * k);
        if (has2) {
            #pragma unroll
            for (int k = 0; k < 4; ++k) b1[k] = __ldcs(qp1 + lane + 32 * k);
        }

        float s0 = 0.0f, s1 = 0.0f;
        #pragma unroll
        for (int k = 0; k < 4; ++k)
            s0 += b0[k].x * vv[k].x + b0[k].y * vv[k].y
                + b0[k].z * vv[k].z + b0[k].w * vv[k].w;
        if (has2) {
            #pragma unroll
            for (int k = 0; k < 4; ++k)
                s1 += b1[k].x * vv[k].x + b1[k].y * vv[k].y
                    + b1[k].z * vv[k].z + b1[k].w * vv[k].w;
        }

        #pragma unroll
        for (int off = 16; off > 0; off >>= 1) {
            s0 += __shfl_xor_sync(0xffffffffu, s0, off);
            s1 += __shfl_xor_sync(0xffffffffu, s1, off);
        }
        if (lane == 0) {
            erow[ll] = s0 + c;
            if (has2) erow[ll2] = s1 + c;
        }
    }
}

// ---------------------------------------------------------------------------
// Softmax: one CTA (512 threads) per row, single pass, registers only.
// PDL secondary behind energy_kernel.
// ---------------------------------------------------------------------------
#define STHREADS 512
#define SWARPS   (STHREADS / 32)   // 16
__global__ __launch_bounds__(STHREADS)
void softmax_kernel(const int* __restrict__ lens,
                    float*     __restrict__ out) {
    __shared__ float sred[SWARPS];

    const int b    = blockIdx.x;
    const int len  = __ldg(lens + b);
    const int tid  = threadIdx.x;
    const int warp = tid >> 5;
    const int lane = tid & 31;
    const int base = tid * 4;

#if __CUDA_ARCH__ >= 900
    cudaGridDependencySynchronize();      // wait for energy results
#endif

    const float4* __restrict__ erow4 =
        (const float4*)(g_energy + (size_t)b * MAXLEN);

    float4 e = erow4[tid];
    const bool v0 = (base + 0 < len), v1 = (base + 1 < len),
               v2 = (base + 2 < len), v3 = (base + 3 < len);

    float m = -CUDART_INF_F;
    if (v0) m = fmaxf(m, e.x);
    if (v1) m = fmaxf(m, e.y);
    if (v2) m = fmaxf(m, e.z);
    if (v3) m = fmaxf(m, e.w);
    #pragma unroll
    for (int off = 16; off > 0; off >>= 1)
        m = fmaxf(m, __shfl_xor_sync(0xffffffffu, m, off));
    if (lane == 0) sred[warp] = m;
    __syncthreads();
    {
        float mm = sred[lane & (SWARPS - 1)];
        #pragma unroll
        for (int off = 8; off > 0; off >>= 1)
            mm = fmaxf(mm, __shfl_xor_sync(0xffffffffu, mm, off));
        m = mm;
    }
    __syncthreads();

    e.x = v0 ? __expf(e.x - m) : 0.0f;
    e.y = v1 ? __expf(e.y - m) : 0.0f;
    e.z = v2 ? __expf(e.z - m) : 0.0f;
    e.w = v3 ? __expf(e.w - m) : 0.0f;
    float ssum = e.x + e.y + e.z + e.w;
    #pragma unroll
    for (int off = 16; off > 0; off >>= 1)
        ssum += __shfl_xor_sync(0xffffffffu, ssum, off);
    if (lane == 0) sred[warp] = ssum;
    __syncthreads();
    {
        float t = sred[lane & (SWARPS - 1)];
        #pragma unroll
        for (int off = 8; off > 0; off >>= 1)
            t += __shfl_xor_sync(0xffffffffu, t, off);
        ssum = t;
    }
    const float inv = 1.0f / ssum;

    float4 o;
    o.x = e.x * inv; o.y = e.y * inv; o.z = e.z * inv; o.w = e.w * inv;
    ((float4*)(out + (size_t)b * MAXLEN))[tid] = o;
}

// ---------------------------------------------------------------------------
// Launch with PDL chaining: prep -> energy -> softmax.
// inputs: questions, questions_lens, lin_w, lin_b, weight_vec
// ---------------------------------------------------------------------------
extern "C" void kernel_launch(void* const* d_in, const int* in_sizes, int n_in,
                              void* d_out, int out_size) {
    const float* questions = (const float*)d_in[0];
    const int*   lens      = (const int*)  d_in[1];
    const float* lin_w     = (const float*)d_in[2];
    const float* lin_b     = (const float*)d_in[3];
    const float* wv        = (const float*)d_in[4];
    float* out = (float*)d_out;

    prep_kernel<<<PBLK, EMBED>>>(lin_w, lin_b, wv);

    cudaLaunchAttribute pdl[1];
    pdl[0].id = cudaLaunchAttributeProgrammaticStreamSerialization;
    pdl[0].val.programmaticStreamSerializationAllowed = 1;

    {
        cudaLaunchConfig_t cfg = {};
        cfg.gridDim  = dim3(NTILES, B2, 1);
        cfg.blockDim = dim3(ETHREADS, 1, 1);
        cfg.stream   = 0;
        cfg.attrs    = pdl;
        cfg.numAttrs = 1;
        cudaLaunchKernelEx(&cfg, energy_kernel, questions, lens);
    }
    {
        cudaLaunchConfig_t cfg = {};
        cfg.gridDim  = dim3(B2, 1, 1);
        cfg.blockDim = dim3(STHREADS, 1, 1);
        cfg.stream   = 0;
        cfg.attrs    = pdl;
        cfg.numAttrs = 1;
        cudaLaunchKernelEx(&cfg, softmax_kernel, lens, out);
    }
}